// round 17
// baseline (speedup 1.0000x reference)
#include <cuda_runtime.h>
#include <cstdint>

// VolSDF volume renderer — FINAL (best measured: 29.15 us, rel_err 8.0e-8).
// Inputs: distance [M,128,1] f32, color [M,128,3] f32, depth_values [M,128] f32
// Output: out_color [M,3] f32 followed by geometry [M,3] f32 (zeros).
//
// One warp per ray; lane l owns samples [4l, 4l+4).
// - Weights telescoped: w_i = e^{-prefix_i} - e^{-cs_i} (one expf per
//   boundary; 6 expf/thread instead of 12).
// - Sample 127 (FAR_DELTA=1e10 sentinel): the reference (jax/XLA) computes
//   its float32 cumsum as a BLOCKED scan (chunk=16), so
//     q = fl( fl(S[0:112) + fl(S[112:127) + sd127)) - sd127 ),
//   applied branchlessly via selects (validated across rounds: rel_err 8e-8).
// - shfl_xor butterfly RGB reduction (redux.f32 not in sm_103 ISA).
// - __ldcs streaming loads; 256-thread blocks, min 8 blocks/SM (full
//   2048-thr/SM occupancy ceiling with finer CTA granularity).
// - Geometry zeros written in-kernel (no separate memset graph node).
// Kernel is HBM-streaming-bound: 168 MB reads @ ~5.8 TB/s effective.

#define FAR_DELTA_ 1e10f

__device__ __forceinline__ float sdf_density(float d) {
    float s = -d;
    float a = fabsf(s) / 0.05f;
    float e = expf(-a);
    return (s <= 0.0f) ? __fmul_rn(10.0f, __fmul_rn(0.5f, e))
                       : __fmul_rn(10.0f, __fsub_rn(1.0f, __fmul_rn(0.5f, e)));
}

__device__ __forceinline__ float4 ldcs4(const float* p) {
    return __ldcs(reinterpret_cast<const float4*>(p));
}

__global__ void __launch_bounds__(256, 8) volsdf_render_kernel(
    const float* __restrict__ dist,
    const float* __restrict__ color,
    const float* __restrict__ depth,
    float* __restrict__ out,
    int M)
{
    const int gtid = blockIdx.x * blockDim.x + threadIdx.x;
    const int ray  = gtid >> 5;
    const int lane = gtid & 31;
    if (ray >= M) return;

    const unsigned FULL = 0xffffffffu;
    // 32-bit offsets: max color index = M*384 < 2^31 for M = 65536
    const int base  = ray * 128 + lane * 4;
    const int cbase = ray * 384 + lane * 12;

    const float4 d4 = ldcs4(dist  + base);
    const float4 z4 = ldcs4(depth + base);
    const float4 c0 = ldcs4(color + cbase + 0);
    const float4 c1 = ldcs4(color + cbase + 4);
    const float4 c2 = ldcs4(color + cbase + 8);

    // geometry output zeros, overlapped with in-flight loads
    if (lane == 1) {
        const int gb = M * 3 + ray * 3;
        out[gb + 0] = 0.0f; out[gb + 1] = 0.0f; out[gb + 2] = 0.0f;
    }

    const float z_next = __shfl_down_sync(FULL, z4.x, 1);

    const float del0 = __fsub_rn(z4.y, z4.x);
    const float del1 = __fsub_rn(z4.z, z4.y);
    const float del2 = __fsub_rn(z4.w, z4.z);
    const float del3 = (lane == 31) ? FAR_DELTA_ : __fsub_rn(z_next, z4.w);

    const float sd0 = __fmul_rn(sdf_density(d4.x), del0);
    const float sd1 = __fmul_rn(sdf_density(d4.y), del1);
    const float sd2 = __fmul_rn(sdf_density(d4.z), del2);
    const float sd3 = __fmul_rn(sdf_density(d4.w), del3);

    const float lsum = __fadd_rn(__fadd_rn(__fadd_rn(sd0, sd1), sd2), sd3);

    // warp inclusive scan of per-lane sums (Kogge-Stone)
    float x = lsum;
    #pragma unroll
    for (int off = 1; off < 32; off <<= 1) {
        float y = __shfl_up_sync(FULL, x, off);
        if (lane >= off) x += y;
    }
    // exclusive prefix via shfl (no subtraction: lane 31's lsum is ~1e11)
    float run = __shfl_up_sync(FULL, x, 1);
    if (lane == 0) run = 0.0f;

    // snapshots for the sample-127 blocked-scan combine
    const float x27 = __shfl_sync(FULL, x, 27);   // S[0:112)
    const float x30 = __shfl_sync(FULL, x, 30);   // S[0:124)

    // inclusive per-sample prefixes (reference rounding)
    const float cs0 = __fadd_rn(run, sd0);
    const float cs1 = __fadd_rn(cs0, sd1);
    const float cs2 = __fadd_rn(cs1, sd2);

    // sample-127 blocked-scan prefix (every lane computes; only lane 31 uses)
    const float Lloc  = __fadd_rn(__fsub_rn(x30, x27),
                                  __fadd_rn(__fadd_rn(sd0, sd1), sd2));
    const float local = __fadd_rn(Lloc, sd3);
    const float csq   = __fadd_rn(x27, local);
    const float q     = __fsub_rn(csq, sd3);

    const float a3 = (lane == 31) ? q : cs2;              // prefix for sample 3
    const float b3 = __fadd_rn(a3, sd3);                  // prefix + sd3

    // telescoping transmittances: one expf per boundary
    const float Ep = expf(-run);
    const float E0 = expf(-cs0);
    const float E1 = expf(-cs1);
    const float E2 = expf(-cs2);
    const float Ea = expf(-a3);
    const float Eb = expf(-b3);

    const float w0 = Ep - E0;
    const float w1 = E0 - E1;
    const float w2 = E1 - E2;
    const float w3 = Ea - Eb;

    float r = w0 * c0.x + w1 * c0.w + w2 * c1.z + w3 * c2.y;
    float g = w0 * c0.y + w1 * c1.x + w2 * c1.w + w3 * c2.z;
    float b = w0 * c0.z + w1 * c1.y + w2 * c2.x + w3 * c2.w;

    // warp reduction of RGB (butterfly)
    #pragma unroll
    for (int off = 16; off > 0; off >>= 1) {
        r += __shfl_xor_sync(FULL, r, off);
        g += __shfl_xor_sync(FULL, g, off);
        b += __shfl_xor_sync(FULL, b, off);
    }

    if (lane == 0) {
        const int ob = ray * 3;
        out[ob + 0] = r;
        out[ob + 1] = g;
        out[ob + 2] = b;
    }
}

extern "C" void kernel_launch(void* const* d_in, const int* in_sizes, int n_in,
                              void* d_out, int out_size) {
    const float* dist  = (const float*)d_in[0];   // [M,128,1]
    const float* color = (const float*)d_in[1];   // [M,128,3]
    const float* depth = (const float*)d_in[2];   // [M,128]

    const int M = in_sizes[2] / 128;
    float* out = (float*)d_out;

    // Kernel writes out_color and geometry zeros; memset only any tail beyond.
    const long long expected = (long long)M * 6;
    if ((long long)out_size > expected) {
        cudaMemsetAsync(out + expected, 0,
                        ((long long)out_size - expected) * sizeof(float), 0);
    }

    const int threads = 256;              // 8 warps -> 8 rays per block
    const int blocks  = (M + 7) / 8;
    volsdf_render_kernel<<<blocks, threads>>>(dist, color, depth, out, M);
}